// round 13
// baseline (speedup 1.0000x reference)
#include <cuda_runtime.h>

#define NB   8
#define NC   256
#define NH   96
#define NW   96
#define HW_  (NH * NW)          // 9216
#define CHW_ (NC * HW_)
#define TPB  128
#define NBLK (NB * HW_ / TPB)   // 576, single wave, blocks never straddle b

// Weights: per channel 9 float4 corner quads (as R5, rel_err 3.6e-7 verified).
#define QSTRIDE 36
// Staged x: 4 rows x 98 cols (1 col zero-pad each side), rows r0-1 .. r0+2.
#define XS    98
#define XROWS 4
#define XSZ   (XROWS * XS)      // 392

__global__ __launch_bounds__(TPB)
void sdw_kernel(const float* __restrict__ x,
                const float* __restrict__ rot,
                const float* __restrict__ wgt,
                float* __restrict__ out)
{
    __shared__ __align__(16) float wsm[NC * QSTRIDE];   // 36 KB
    __shared__ float xsm[2][XSZ];                       // 3.1 KB

    const int tid = threadIdx.x;

    // Build weight quads: quad(yq,xb) = rows(yq,yq+1) x cols(xb,xb+1).
    for (int i = tid; i < NC * 9; i += TPB) {
        int c = i / 9, q = i % 9;
        int yq = q / 3, xb = q % 3;
        const float* wc = wgt + c * 16;
        float4 v;
        v.x = wc[yq * 4 + xb];
        v.y = wc[yq * 4 + xb + 1];
        v.z = wc[yq * 4 + xb + 4];
        v.w = wc[yq * 4 + xb + 5];
        *reinterpret_cast<float4*>(&wsm[c * QSTRIDE + q * 4]) = v;
    }

    const int blk  = blockIdx.x;
    const int b    = blk / (HW_ / TPB);
    const int pix0 = (blk % (HW_ / TPB)) * TPB;
    const int pix  = pix0 + tid;
    const int h = pix / NW, w = pix % NW;
    const int r0 = pix0 / NW;            // block pixels span rows r0, r0+1 only

    // Per-tap: 4 combined bilinear coefficients + quad word-offset.
    float c00[9], c01[9], c10[9], c11[9];
    int qo[9];

    const float* rbase = rot + (b * 18) * HW_ + pix;
    #pragma unroll
    for (int kh = 0; kh < 3; kh++) {
        #pragma unroll
        for (int kw = 0; kw < 3; kw++) {
            const int t = kh * 3 + kw;
            float ryv = __ldg(rbase + (2 * t) * HW_);
            float rxv = __ldg(rbase + (2 * t + 1) * HW_);
            float py = (kh + 0.5f) * (4.0f / 3.0f) - 0.5f + ryv;
            float px = (kw + 0.5f) * (4.0f / 3.0f) - 0.5f + rxv;
            float fpy = floorf(py), fpx = floorf(px);
            int iy = (int)fpy, ix = (int)fpx;
            float fy = py - fpy, fx = px - fpx;
            float ry0 = (iy >= 0  && iy < 4) ? (1.f - fy) : 0.f;
            float ry1 = (iy >= -1 && iy < 3) ? fy         : 0.f;
            float rx0 = (ix >= 0  && ix < 4) ? (1.f - fx) : 0.f;
            float rx1 = (ix >= -1 && ix < 3) ? fx         : 0.f;
            int xb = min(max(ix, 0), 2);
            int dx = ix - xb;
            float e0 = (dx == 0) ? rx0 : ((dx == -1) ? rx1 : 0.f);
            float e1 = (dx == 0) ? rx1 : ((dx ==  1) ? rx0 : 0.f);
            int yq = min(max(iy, 0), 2);
            int dy = iy - yq;
            float f0 = (dy == 0) ? ry0 : ((dy == -1) ? ry1 : 0.f);
            float f1 = (dy == 0) ? ry1 : ((dy ==  1) ? ry0 : 0.f);
            c00[t] = f0 * e0; c01[t] = f0 * e1;
            c10[t] = f1 * e0; c11[t] = f1 * e1;
            qo[t] = (yq * 3 + xb) * 4;
        }
    }

    // Staging-slot map: thread owns slots tid + j*TPB (j=0..3); slot s ->
    // staged row ri = s/XS (global row r0-1+ri), staged col ci (global ci-1).
    // Out-of-image slots are zero-filled (implements the conv zero padding).
    int  fo[4];
    bool fv[4];
    #pragma unroll
    for (int j = 0; j < 4; j++) {
        int s = tid + j * TPB;
        int ri = s / XS, ci = s - ri * XS;
        int gr = r0 - 1 + ri, gc = ci - 1;
        fv[j] = (s < XSZ) && (gr >= 0) && (gr < NH) && (gc >= 0) && (gc < NW);
        fo[j] = fv[j] ? (gr * NW + gc) : 0;
    }

    const float* xb_ = x + b * CHW_;
    float* op = out + b * CHW_ + pix;

    // Prologue: stage channel 0 into buffer 0.
    float pf[4];
    #pragma unroll
    for (int j = 0; j < 4; j++) pf[j] = fv[j] ? __ldg(xb_ + fo[j]) : 0.f;
    #pragma unroll
    for (int j = 0; j < 4; j++) {
        int s = tid + j * TPB;
        if (s < XSZ) xsm[0][s] = pf[j];
    }
    __syncthreads();

    // Tap read address: staged row (h-r0+kh), staged col (w+kw).
    const int lrbase = (h - r0) * XS + w;

    for (int c = 0; c < NC; ++c) {
        const int cur = c & 1;
        // Prefetch channel c+1 into registers (lands during compute below).
        if (c + 1 < NC) {
            const float* xc1 = xb_ + (c + 1) * HW_;
            #pragma unroll
            for (int j = 0; j < 4; j++) pf[j] = fv[j] ? __ldg(xc1 + fo[j]) : 0.f;
        }
        // Compute channel c entirely from shared memory.
        const float* xc = xsm[cur];
        const float* wb = wsm + c * QSTRIDE;
        float acc = 0.f;
        #pragma unroll
        for (int kh = 0; kh < 3; kh++) {
            #pragma unroll
            for (int kw = 0; kw < 3; kw++) {
                const int t = kh * 3 + kw;
                float4 q = *reinterpret_cast<const float4*>(wb + qo[t]);
                float g = c00[t] * q.x + c01[t] * q.y
                        + c10[t] * q.z + c11[t] * q.w;
                float xv = xc[lrbase + kh * XS + kw];
                acc = fmaf(g, xv, acc);
            }
        }
        op[c * HW_] = acc;
        // Publish the prefetched channel into the other buffer.
        if (c + 1 < NC) {
            #pragma unroll
            for (int j = 0; j < 4; j++) {
                int s = tid + j * TPB;
                if (s < XSZ) xsm[cur ^ 1][s] = pf[j];
            }
        }
        __syncthreads();
    }
}

extern "C" void kernel_launch(void* const* d_in, const int* in_sizes, int n_in,
                              void* d_out, int out_size)
{
    const float* x   = (const float*)d_in[0];
    const float* rot = (const float*)d_in[1];
    const float* wgt = (const float*)d_in[2];
    float* out = (float*)d_out;
    sdw_kernel<<<NBLK, TPB>>>(x, rot, wgt, out);
}

// round 15
// speedup vs baseline: 1.6384x; 1.6384x over previous
#include <cuda_runtime.h>

#define NB   8
#define NC   256
#define NH   96
#define NW   96
#define HW_  (NH * NW)          // 9216
#define CHW_ (NC * HW_)
#define NTOT (NB * CHW_)
#define TPB  128
#define NBLK (NB * HW_ / TPB)   // 576

// Per channel: 9 float4 quads, quad(yq, xb) = { w[yq][xb], w[yq][xb+1],
//                                              w[yq+1][xb], w[yq+1][xb+1] }
#define QSTRIDE 36

__global__ __launch_bounds__(TPB)
void sdw_kernel(const float* __restrict__ x,
                const float* __restrict__ rot,
                const float* __restrict__ wgt,
                float* __restrict__ out)
{
    __shared__ __align__(16) float wsm[NC * QSTRIDE];

    const int tid = threadIdx.x;
    for (int i = tid; i < NC * 9; i += TPB) {
        int c = i / 9, q = i % 9;
        int yq = q / 3, xb = q % 3;
        const float* wc = wgt + c * 16;
        float4 v;
        v.x = wc[yq * 4 + xb];
        v.y = wc[yq * 4 + xb + 1];
        v.z = wc[yq * 4 + xb + 4];
        v.w = wc[yq * 4 + xb + 5];
        *reinterpret_cast<float4*>(&wsm[c * QSTRIDE + q * 4]) = v;
    }
    __syncthreads();

    const int blk = blockIdx.x;
    const int b   = blk / (HW_ / TPB);
    const int pix = (blk % (HW_ / TPB)) * TPB + tid;
    const int h = pix / NW, w = pix % NW;

    float c00[9], c01[9], c10[9], c11[9];
    int qo[9];

    const float* rbase = rot + (b * 18) * HW_ + pix;
    #pragma unroll
    for (int kh = 0; kh < 3; kh++) {
        #pragma unroll
        for (int kw = 0; kw < 3; kw++) {
            const int t = kh * 3 + kw;
            float ryv = __ldg(rbase + (2 * t) * HW_);
            float rxv = __ldg(rbase + (2 * t + 1) * HW_);
            float py = (kh + 0.5f) * (4.0f / 3.0f) - 0.5f + ryv;
            float px = (kw + 0.5f) * (4.0f / 3.0f) - 0.5f + rxv;
            float fpy = floorf(py), fpx = floorf(px);
            int iy = (int)fpy, ix = (int)fpx;
            float fy = py - fpy, fx = px - fpx;
            float ry0 = (iy >= 0  && iy < 4) ? (1.f - fy) : 0.f;
            float ry1 = (iy >= -1 && iy < 3) ? fy         : 0.f;
            float rx0 = (ix >= 0  && ix < 4) ? (1.f - fx) : 0.f;
            float rx1 = (ix >= -1 && ix < 3) ? fx         : 0.f;
            int xb = min(max(ix, 0), 2);
            int dx = ix - xb;
            float e0 = (dx == 0) ? rx0 : ((dx == -1) ? rx1 : 0.f);
            float e1 = (dx == 0) ? rx1 : ((dx ==  1) ? rx0 : 0.f);
            int yq = min(max(iy, 0), 2);
            int dy = iy - yq;
            float f0 = (dy == 0) ? ry0 : ((dy == -1) ? ry1 : 0.f);
            float f1 = (dy == 0) ? ry1 : ((dy ==  1) ? ry0 : 0.f);
            int hh = h + kh - 1, ww = w + kw - 1;
            float xval = (hh >= 0 && hh < NH && ww >= 0 && ww < NW) ? 1.f : 0.f;
            f0 *= xval; f1 *= xval;
            c00[t] = f0 * e0; c01[t] = f0 * e1;
            c10[t] = f1 * e0; c11[t] = f1 * e1;
            qo[t] = (yq * 3 + xb) * 4;
        }
    }

    const int off0 = b * CHW_ + pix;
    const bool guard = (blk == 0) || (blk == NBLK - 1);

    if (!guard) {
        const float* xp = x + off0;
        float* op = out + off0;
        int wbase = 0;
        // 4 explicitly independent channel streams per iteration: 4 LDG/LDS
        // chains + 4 accumulators for ptxas to front-batch (MLP ~36).
        for (int c = 0; c < NC; c += 4) {
            float acc0 = 0.f, acc1 = 0.f, acc2 = 0.f, acc3 = 0.f;
            #pragma unroll
            for (int kh = 0; kh < 3; kh++) {
                #pragma unroll
                for (int kw = 0; kw < 3; kw++) {
                    const int t = kh * 3 + kw;
                    const int xoff = (kh - 1) * NW + (kw - 1);
                    const int wq = wbase + qo[t];
                    float4 q0 = *reinterpret_cast<const float4*>(&wsm[wq]);
                    float4 q1 = *reinterpret_cast<const float4*>(&wsm[wq + QSTRIDE]);
                    float4 q2 = *reinterpret_cast<const float4*>(&wsm[wq + 2 * QSTRIDE]);
                    float4 q3 = *reinterpret_cast<const float4*>(&wsm[wq + 3 * QSTRIDE]);
                    float xv0 = __ldg(xp + xoff);
                    float xv1 = __ldg(xp + xoff + HW_);
                    float xv2 = __ldg(xp + xoff + 2 * HW_);
                    float xv3 = __ldg(xp + xoff + 3 * HW_);
                    float g0 = c00[t] * q0.x + c01[t] * q0.y + c10[t] * q0.z + c11[t] * q0.w;
                    float g1 = c00[t] * q1.x + c01[t] * q1.y + c10[t] * q1.z + c11[t] * q1.w;
                    float g2 = c00[t] * q2.x + c01[t] * q2.y + c10[t] * q2.z + c11[t] * q2.w;
                    float g3 = c00[t] * q3.x + c01[t] * q3.y + c10[t] * q3.z + c11[t] * q3.w;
                    acc0 = fmaf(g0, xv0, acc0);
                    acc1 = fmaf(g1, xv1, acc1);
                    acc2 = fmaf(g2, xv2, acc2);
                    acc3 = fmaf(g3, xv3, acc3);
                }
            }
            op[0]       = acc0;
            op[HW_]     = acc1;
            op[2 * HW_] = acc2;
            op[3 * HW_] = acc3;
            wbase += 4 * QSTRIDE; xp += 4 * HW_; op += 4 * HW_;
        }
    } else {
        float* op = out + off0;
        int off = off0;
        int wbase = 0;
        for (int c = 0; c < NC; c += 4) {
            float acc0 = 0.f, acc1 = 0.f, acc2 = 0.f, acc3 = 0.f;
            #pragma unroll
            for (int kh = 0; kh < 3; kh++) {
                #pragma unroll
                for (int kw = 0; kw < 3; kw++) {
                    const int t = kh * 3 + kw;
                    const int xoff = (kh - 1) * NW + (kw - 1);
                    const int wq = wbase + qo[t];
                    float4 q0 = *reinterpret_cast<const float4*>(&wsm[wq]);
                    float4 q1 = *reinterpret_cast<const float4*>(&wsm[wq + QSTRIDE]);
                    float4 q2 = *reinterpret_cast<const float4*>(&wsm[wq + 2 * QSTRIDE]);
                    float4 q3 = *reinterpret_cast<const float4*>(&wsm[wq + 3 * QSTRIDE]);
                    int o = off + xoff;
                    float xv0 = (o >= 0 && o < NTOT) ? x[o] : 0.f;
                    int o1 = o + HW_;
                    float xv1 = (o1 >= 0 && o1 < NTOT) ? x[o1] : 0.f;
                    int o2 = o + 2 * HW_;
                    float xv2 = (o2 >= 0 && o2 < NTOT) ? x[o2] : 0.f;
                    int o3 = o + 3 * HW_;
                    float xv3 = (o3 >= 0 && o3 < NTOT) ? x[o3] : 0.f;
                    float g0 = c00[t] * q0.x + c01[t] * q0.y + c10[t] * q0.z + c11[t] * q0.w;
                    float g1 = c00[t] * q1.x + c01[t] * q1.y + c10[t] * q1.z + c11[t] * q1.w;
                    float g2 = c00[t] * q2.x + c01[t] * q2.y + c10[t] * q2.z + c11[t] * q2.w;
                    float g3 = c00[t] * q3.x + c01[t] * q3.y + c10[t] * q3.z + c11[t] * q3.w;
                    acc0 = fmaf(g0, xv0, acc0);
                    acc1 = fmaf(g1, xv1, acc1);
                    acc2 = fmaf(g2, xv2, acc2);
                    acc3 = fmaf(g3, xv3, acc3);
                }
            }
            op[0]       = acc0;
            op[HW_]     = acc1;
            op[2 * HW_] = acc2;
            op[3 * HW_] = acc3;
            wbase += 4 * QSTRIDE; off += 4 * HW_; op += 4 * HW_;
        }
    }
}

extern "C" void kernel_launch(void* const* d_in, const int* in_sizes, int n_in,
                              void* d_out, int out_size)
{
    const float* x   = (const float*)d_in[0];
    const float* rot = (const float*)d_in[1];
    const float* wgt = (const float*)d_in[2];
    float* out = (float*)d_out;
    sdw_kernel<<<NBLK, TPB>>>(x, rot, wgt, out);
}